// round 16
// baseline (speedup 1.0000x reference)
#include <cuda_runtime.h>
#include <cuda_bf16.h>
#include <cstdint>
#include <cstddef>

// Problem constants
#define NN 100000      // nodes
#define NE 800000      // edges
#define HD 256         // hidden dim
#define NL 6           // layers
#define W1_LD 259      // H + 3 edge features
#define W2_LD 512      // H + INTER
#define HP 128         // packed pairs per node row (HD/2)

// ---------------- scratch (device globals; no runtime allocation) ----------
__device__ float g_P [(size_t)NN * HD];
__device__ uint2 g_hPkA[(size_t)NN * HP];
__device__ uint2 g_hPkB[(size_t)NN * HP];
__device__ uint2 g_hNp [(size_t)NN * HP];
__device__ uint2 g_W1p [NL * 256 * 128];
__device__ uint2 g_W2p [NL * 256 * 256];
__device__ uint2 g_Wh1p[256 * 128];
__device__ int   g_offs[NN + 1];
__device__ int   g_cursor[NN];
__device__ int   g_eidx[NE];
__device__ int   g_bsum[512];

// split a,b into bf16 (hi, lo) packed words
__device__ __forceinline__ void split2(float a, float b, uint32_t& hi, uint32_t& lo) {
    __nv_bfloat16 ha = __float2bfloat16(a);
    __nv_bfloat16 hb = __float2bfloat16(b);
    __nv_bfloat16 la = __float2bfloat16(a - __bfloat162float(ha));
    __nv_bfloat16 lb = __float2bfloat16(b - __bfloat162float(hb));
    __nv_bfloat162 h2 = __halves2bfloat162(ha, hb);
    __nv_bfloat162 l2 = __halves2bfloat162(la, lb);
    hi = *reinterpret_cast<uint32_t*>(&h2);
    lo = *reinterpret_cast<uint32_t*>(&l2);
}

__device__ __forceinline__ void mma_bf16(float* c,
                                         uint32_t a0, uint32_t a1, uint32_t a2, uint32_t a3,
                                         uint32_t b0, uint32_t b1) {
    asm volatile(
        "mma.sync.aligned.m16n8k16.row.col.f32.bf16.bf16.f32 "
        "{%0,%1,%2,%3}, {%4,%5,%6,%7}, {%8,%9}, {%0,%1,%2,%3};"
        : "+f"(c[0]), "+f"(c[1]), "+f"(c[2]), "+f"(c[3])
        : "r"(a0), "r"(a1), "r"(a2), "r"(a3), "r"(b0), "r"(b1));
}

__device__ __forceinline__ void cp_async16(uint32_t smem_dst, const void* gsrc) {
    asm volatile("cp.async.cg.shared.global [%0], [%1], 16;"
                 :: "r"(smem_dst), "l"(gsrc) : "memory");
}
#define CP_COMMIT() asm volatile("cp.async.commit_group;" ::: "memory")
#define CP_WAIT0()  asm volatile("cp.async.wait_group 0;" ::: "memory")
#define CP_WAIT1()  asm volatile("cp.async.wait_group 1;" ::: "memory")

// ---------------- setup kernels --------------------------------------------
__global__ void init_kernel(const int* __restrict__ gt,
                            const float* __restrict__ emb,
                            uint2* __restrict__ hp,
                            float* __restrict__ outv,
                            const float* __restrict__ bh2) {
    int i = blockIdx.x * blockDim.x + threadIdx.x;
    if (i < NN * HP) {
        int node = i >> 7;
        int j    = i & 127;
        const float* e = emb + gt[node] * HD + 2 * j;
        uint32_t hi, lo;
        split2(e[0], e[1], hi, lo);
        hp[i] = make_uint2(hi, lo);
    }
    if (i < NN) outv[i] = bh2[0];     // out pre-initialized for fused head dot
}

__global__ void zero_int(int* __restrict__ p, int n) {
    int i = blockIdx.x * blockDim.x + threadIdx.x;
    if (i < n) p[i] = 0;
}

__global__ void count_kernel(const int* __restrict__ dst, int* __restrict__ ideg) {
    int e = blockIdx.x * blockDim.x + threadIdx.x;
    if (e < NE) atomicAdd(&ideg[dst[e]], 1);
}

#define SB 512
__global__ void scan_block(const int* __restrict__ in, int* __restrict__ outEx,
                           int* __restrict__ bsum, int n) {
    __shared__ int s[SB];
    int i = blockIdx.x * SB + threadIdx.x;
    int v = (i < n) ? in[i] : 0;
    s[threadIdx.x] = v;
    __syncthreads();
    for (int d = 1; d < SB; d <<= 1) {
        int t = (threadIdx.x >= (unsigned)d) ? s[threadIdx.x - d] : 0;
        __syncthreads();
        s[threadIdx.x] += t;
        __syncthreads();
    }
    if (i < n) outEx[i] = s[threadIdx.x] - v;
    if (threadIdx.x == SB - 1) bsum[blockIdx.x] = s[SB - 1];
}

__global__ void scan_tops(int* __restrict__ bsum, int nb) {
    __shared__ int s[SB];
    int v = (threadIdx.x < (unsigned)nb) ? bsum[threadIdx.x] : 0;
    s[threadIdx.x] = v;
    __syncthreads();
    for (int d = 1; d < SB; d <<= 1) {
        int t = (threadIdx.x >= (unsigned)d) ? s[threadIdx.x - d] : 0;
        __syncthreads();
        s[threadIdx.x] += t;
        __syncthreads();
    }
    if (threadIdx.x < (unsigned)nb) bsum[threadIdx.x] = s[threadIdx.x] - v;
}

__global__ void scan_add(int* __restrict__ outEx, const int* __restrict__ bsum,
                         int* __restrict__ cursor, int n) {
    int i = blockIdx.x * blockDim.x + threadIdx.x;
    if (i < n) {
        int v = outEx[i] + bsum[i / SB];
        outEx[i] = v;
        cursor[i] = v;
    }
    if (i == 0) outEx[n] = NE;
}

__global__ void fill_kernel(const int* __restrict__ dst, int* __restrict__ cursor,
                            int* __restrict__ eidx) {
    int e = blockIdx.x * blockDim.x + threadIdx.x;
    if (e < NE) {
        int pos = atomicAdd(&cursor[dst[e]], 1);
        eidx[pos] = e;
    }
}

// pack fp32 [rows, srcld] -> uint2 hi/lo [rows, kp] (weights only)
__global__ void pack_kernel(const float* __restrict__ src, int srcld, int kp,
                            int total, uint2* __restrict__ dst) {
    int i = blockIdx.x * blockDim.x + threadIdx.x;
    if (i >= total) return;
    int r = i / kp, j = i - r * kp;
    float a = src[(size_t)r * srcld + 2 * j];
    float b = src[(size_t)r * srcld + 2 * j + 1];
    uint32_t hi, lo;
    split2(a, b, hi, lo);
    dst[(size_t)r * kp + j] = make_uint2(hi, lo);
}

// ---------------- CSR gather (4-edge unrolled, 2 warps/node) ----------------
__global__ __launch_bounds__(256)
void csr_gather_kernel(const int* __restrict__ offs,
                       const int* __restrict__ eidx,
                       const int* __restrict__ src,
                       const float* __restrict__ w,
                       const float* __restrict__ P,
                       const float* __restrict__ W1b,
                       uint2* __restrict__ hNp) {
    __shared__ float sW[3 * HD];
    for (int i = threadIdx.x; i < HD; i += blockDim.x) {
        sW[i]          = W1b[(size_t)i * W1_LD + 0];
        sW[HD + i]     = W1b[(size_t)i * W1_LD + 1];
        sW[2 * HD + i] = W1b[(size_t)i * W1_LD + 2];
    }
    __syncthreads();

    int gw = blockIdx.x * 8 + (threadIdx.x >> 5);   // global warp id
    int lane = threadIdx.x & 31;
    if (gw >= NN * 2) return;
    int node = gw >> 1;
    int half = gw & 1;
    int c = half * 128 + lane * 4;

    float wa0 = sW[c],        wa1 = sW[c+1],        wa2 = sW[c+2],        wa3 = sW[c+3];
    float wb0 = sW[HD+c],     wb1 = sW[HD+c+1],     wb2 = sW[HD+c+2],     wb3 = sW[HD+c+3];
    float wc0 = sW[2*HD+c],   wc1 = sW[2*HD+c+1],   wc2 = sW[2*HD+c+2],   wc3 = sW[2*HD+c+3];

    int beg = offs[node], end = offs[node + 1];
    float a0 = 0.f, a1 = 0.f, a2 = 0.f, a3 = 0.f;

    for (int e = beg; e < end; e += 4) {
        int last = end - 1;
        int i1 = e + 1 <= last ? e + 1 : last;
        int i2 = e + 2 <= last ? e + 2 : last;
        int i3 = e + 3 <= last ? e + 3 : last;
        float m1 = e + 1 < end ? 1.f : 0.f;
        float m2 = e + 2 < end ? 1.f : 0.f;
        float m3 = e + 3 < end ? 1.f : 0.f;

        int ed0 = eidx[e],  ed1 = eidx[i1], ed2 = eidx[i2], ed3 = eidx[i3];
        int s0 = src[ed0], s1 = src[ed1], s2 = src[ed2], s3 = src[ed3];
        float e00 = w[ed0*3], e01 = w[ed0*3+1], e02 = w[ed0*3+2];
        float e10 = w[ed1*3], e11 = w[ed1*3+1], e12 = w[ed1*3+2];
        float e20 = w[ed2*3], e21 = w[ed2*3+1], e22 = w[ed2*3+2];
        float e30 = w[ed3*3], e31 = w[ed3*3+1], e32 = w[ed3*3+2];
        float4 p0 = *(const float4*)(P + (size_t)s0 * HD + c);
        float4 p1 = *(const float4*)(P + (size_t)s1 * HD + c);
        float4 p2 = *(const float4*)(P + (size_t)s2 * HD + c);
        float4 p3 = *(const float4*)(P + (size_t)s3 * HD + c);

        float t;
        t = p0.x + e00*wa0 + e01*wb0 + e02*wc0; a0 +=      (t > 0.f ? t : 0.01f*t);
        t = p0.y + e00*wa1 + e01*wb1 + e02*wc1; a1 +=      (t > 0.f ? t : 0.01f*t);
        t = p0.z + e00*wa2 + e01*wb2 + e02*wc2; a2 +=      (t > 0.f ? t : 0.01f*t);
        t = p0.w + e00*wa3 + e01*wb3 + e02*wc3; a3 +=      (t > 0.f ? t : 0.01f*t);
        t = p1.x + e10*wa0 + e11*wb0 + e12*wc0; a0 += m1 * (t > 0.f ? t : 0.01f*t);
        t = p1.y + e10*wa1 + e11*wb1 + e12*wc1; a1 += m1 * (t > 0.f ? t : 0.01f*t);
        t = p1.z + e10*wa2 + e11*wb2 + e12*wc2; a2 += m1 * (t > 0.f ? t : 0.01f*t);
        t = p1.w + e10*wa3 + e11*wb3 + e12*wc3; a3 += m1 * (t > 0.f ? t : 0.01f*t);
        t = p2.x + e20*wa0 + e21*wb0 + e22*wc0; a0 += m2 * (t > 0.f ? t : 0.01f*t);
        t = p2.y + e20*wa1 + e21*wb1 + e22*wc1; a1 += m2 * (t > 0.f ? t : 0.01f*t);
        t = p2.z + e20*wa2 + e21*wb2 + e22*wc2; a2 += m2 * (t > 0.f ? t : 0.01f*t);
        t = p2.w + e20*wa3 + e21*wb3 + e22*wc3; a3 += m2 * (t > 0.f ? t : 0.01f*t);
        t = p3.x + e30*wa0 + e31*wb0 + e32*wc0; a0 += m3 * (t > 0.f ? t : 0.01f*t);
        t = p3.y + e30*wa1 + e31*wb1 + e32*wc1; a1 += m3 * (t > 0.f ? t : 0.01f*t);
        t = p3.z + e30*wa2 + e31*wb2 + e32*wc2; a2 += m3 * (t > 0.f ? t : 0.01f*t);
        t = p3.w + e30*wa3 + e31*wb3 + e32*wc3; a3 += m3 * (t > 0.f ? t : 0.01f*t);
    }

    float inv = 1.0f / fmaxf((float)(end - beg), 1.0f);
    a0 *= inv; a1 *= inv; a2 *= inv; a3 *= inv;

    uint32_t hi, lo;
    uint2* outp = hNp + (size_t)node * HP + half * 64 + lane * 2;
    split2(a0, a1, hi, lo); outp[0] = make_uint2(hi, lo);
    split2(a2, a3, hi, lo); outp[1] = make_uint2(hi, lo);
}

// ---------------- tensor-core bf16 GEMM: 3-stage cp.async pipeline ----------
#define BM 128
#define BN 64
#define KC 32
#define RW 32                   // 32-bit words per row
#define ASZ (BM * RW)           // words per A stage (16 KB)
#define BSZ (BN * RW)           // words per B stage (8 KB)
#define SMEM_BYTES (3 * (ASZ + BSZ) * 4)   // 72 KB dynamic

__global__ __launch_bounds__(256, 3)
void mma_gemm_kernel(const uint2* __restrict__ A1, int K1,
                     const uint2* __restrict__ A2, int K2,
                     const uint2* __restrict__ Bp,
                     const float* __restrict__ bias,
                     float* __restrict__ C, uint2* __restrict__ Cp,
                     const float* __restrict__ Wh2, float* __restrict__ outv,
                     int M, int N, int act) {
    extern __shared__ uint32_t dyn[];
    uint32_t* AwS = dyn;                // 3 stages of A, contiguous
    uint32_t* BwS = dyn + 3 * ASZ;      // 3 stages of B

    int tid  = threadIdx.x;
    int wid  = tid >> 5;
    int lane = tid & 31;
    int grp  = lane >> 2;
    int tg   = lane & 3;
    int warp_m = wid & 3;
    int warp_n = wid >> 2;
    int m0 = warp_m * 32;
    int n0 = warp_n * 32;
    int mBase = blockIdx.y * BM;
    int nBase = blockIdx.x * BN;

    int K = K1 + K2;
    int nch = K / KC;
    int k1ch = K1 / KC;
    int kpB = K >> 1;

    uint32_t aSm[3], bSm[3];
#pragma unroll
    for (int s = 0; s < 3; s++) {
        aSm[s] = (uint32_t)__cvta_generic_to_shared(AwS + s * ASZ);
        bSm[s] = (uint32_t)__cvta_generic_to_shared(BwS + s * BSZ);
    }

    float acc[2][4][4];
#pragma unroll
    for (int i = 0; i < 2; i++)
#pragma unroll
        for (int j = 0; j < 4; j++)
#pragma unroll
            for (int q = 0; q < 4; q++) acc[i][j][q] = 0.0f;

    auto load_chunk = [&](int kc, int b) {
        int kp = kc * (KC / 2);
        bool u2 = (kc >= k1ch);
        const uint2* Ap = u2 ? A2 : A1;
        int kpa = u2 ? kp - (K1 >> 1) : kp;
        int lda = (u2 ? K2 : K1) >> 1;
#pragma unroll
        for (int i = 0; i < 4; i++) {
            int job = tid + i * 256;
            int r = job >> 3, s = job & 7;
            int row = mBase + r; if (row >= M) row = M - 1;
            const uint2* g = Ap + (size_t)row * lda + kpa + 2 * s;
            uint32_t d = aSm[b] + (uint32_t)(r * RW + ((4 * s) ^ ((r & 3) << 3))) * 4u;
            cp_async16(d, g);
        }
#pragma unroll
        for (int i = 0; i < 2; i++) {
            int job = tid + i * 256;
            int r = job >> 3, s = job & 7;
            const uint2* g = Bp + (size_t)(nBase + r) * kpB + kp + 2 * s;
            uint32_t d = bSm[b] + (uint32_t)(r * RW + ((4 * s) ^ ((r & 3) << 3))) * 4u;
            cp_async16(d, g);
        }
    };

    // Prologue: two chunks in flight (prefetch distance 2)
    load_chunk(0, 0);
    CP_COMMIT();
    if (nch > 1) { load_chunk(1, 1); CP_COMMIT(); }

    int stC = 0;   // stage of the chunk being computed (kc % 3)
    int stL = 2;   // stage for the next load ((kc+2) % 3)

    for (int kc = 0; kc < nch; kc++) {
        // Steady state: two groups pending {kc, kc+1}; wait until <=1 -> kc done.
        // Last iteration: only {kc} pending; must wait to 0.
        if (kc < nch - 1) CP_WAIT1(); else CP_WAIT0();
        // Single barrier: also guarantees all warps finished computing chunk
        // kc-1 (program order), so its buffer (stage stL) is safe to refill.
        __syncthreads();
        if (kc + 2 < nch) { load_chunk(kc + 2, stL); CP_COMMIT(); }

        const uint32_t* A = AwS + stC * ASZ;
        const uint32_t* Bs = BwS + stC * BSZ;
#pragma unroll
        for (int ks = 0; ks < 2; ks++) {
            uint2 aF[2][4];
#pragma unroll
            for (int mt = 0; mt < 2; mt++) {
                int r = m0 + mt * 16 + grp;
                int sw = (r & 3) << 2;
                int p0 = (ks * 8 + tg) ^ sw;
                int p1 = (ks * 8 + tg + 4) ^ sw;
                aF[mt][0] = *(const uint2*)&A[r * RW + 2 * p0];
                aF[mt][1] = *(const uint2*)&A[(r + 8) * RW + 2 * p0];
                aF[mt][2] = *(const uint2*)&A[r * RW + 2 * p1];
                aF[mt][3] = *(const uint2*)&A[(r + 8) * RW + 2 * p1];
            }
            uint2 bF[4][2];
#pragma unroll
            for (int nt = 0; nt < 4; nt++) {
                int nr = n0 + nt * 8 + grp;
                int sw = (nr & 3) << 2;
                bF[nt][0] = *(const uint2*)&Bs[nr * RW + 2 * ((ks * 8 + tg) ^ sw)];
                bF[nt][1] = *(const uint2*)&Bs[nr * RW + 2 * ((ks * 8 + tg + 4) ^ sw)];
            }
#pragma unroll
            for (int mt = 0; mt < 2; mt++)
#pragma unroll
                for (int nt = 0; nt < 4; nt++) {
                    float* c = acc[mt][nt];
                    mma_bf16(c, aF[mt][0].x, aF[mt][1].x, aF[mt][2].x, aF[mt][3].x,
                             bF[nt][0].x, bF[nt][1].x);
                    mma_bf16(c, aF[mt][0].y, aF[mt][1].y, aF[mt][2].y, aF[mt][3].y,
                             bF[nt][0].x, bF[nt][1].x);
                    mma_bf16(c, aF[mt][0].x, aF[mt][1].x, aF[mt][2].x, aF[mt][3].x,
                             bF[nt][0].y, bF[nt][1].y);
                }
        }
        stC = (stC + 1 == 3) ? 0 : stC + 1;
        stL = (stL + 1 == 3) ? 0 : stL + 1;
    }

    // Epilogue
#pragma unroll
    for (int mt = 0; mt < 2; mt++) {
#pragma unroll
        for (int half = 0; half < 2; half++) {
            int row = mBase + m0 + mt * 16 + grp + half * 8;
            float part = 0.0f;
#pragma unroll
            for (int nt = 0; nt < 4; nt++) {
                int col = nBase + n0 + nt * 8 + 2 * tg;
                float2 v;
                v.x = acc[mt][nt][half * 2 + 0];
                v.y = acc[mt][nt][half * 2 + 1];
                if (bias) { v.x += bias[col]; v.y += bias[col + 1]; }
                if (act)  { v.x = fmaxf(v.x, 0.0f); v.y = fmaxf(v.y, 0.0f); }
                if (outv) {
                    part += v.x * Wh2[col] + v.y * Wh2[col + 1];
                } else if (row < M) {
                    if (Cp) {
                        uint32_t hi, lo;
                        split2(v.x, v.y, hi, lo);
                        Cp[(size_t)row * (N >> 1) + (col >> 1)] = make_uint2(hi, lo);
                    } else {
                        *(float2*)(C + (size_t)row * N + col) = v;
                    }
                }
            }
            if (outv) {
                part += __shfl_xor_sync(0xffffffffu, part, 1);
                part += __shfl_xor_sync(0xffffffffu, part, 2);
                if (tg == 0 && row < M) atomicAdd(&outv[row], part);
            }
        }
    }
}

// ---------------- launch ---------------------------------------------------
extern "C" void kernel_launch(void* const* d_in, const int* in_sizes, int n_in,
                              void* d_out, int out_size) {
    const int*   gate_type = (const int*)  d_in[0];
    const int*   src       = (const int*)  d_in[1];
    const int*   dst       = (const int*)  d_in[2];
    const float* w         = (const float*)d_in[3];
    const float* emb       = (const float*)d_in[4];
    const float* W1        = (const float*)d_in[5];
    const float* W2        = (const float*)d_in[6];
    const float* b2        = (const float*)d_in[7];
    const float* Wh1       = (const float*)d_in[8];
    const float* bh1       = (const float*)d_in[9];
    const float* Wh2       = (const float*)d_in[10];
    const float* bh2       = (const float*)d_in[11];
    float* out = (float*)d_out;

    float *P;
    uint2 *hPkA, *hPkB, *hNp, *W1p, *W2p, *Wh1p;
    int *offs, *cursor, *eidx, *bsum;
    cudaGetSymbolAddress((void**)&P,      g_P);
    cudaGetSymbolAddress((void**)&hPkA,   g_hPkA);
    cudaGetSymbolAddress((void**)&hPkB,   g_hPkB);
    cudaGetSymbolAddress((void**)&hNp,    g_hNp);
    cudaGetSymbolAddress((void**)&W1p,    g_W1p);
    cudaGetSymbolAddress((void**)&W2p,    g_W2p);
    cudaGetSymbolAddress((void**)&Wh1p,   g_Wh1p);
    cudaGetSymbolAddress((void**)&offs,   g_offs);
    cudaGetSymbolAddress((void**)&cursor, g_cursor);
    cudaGetSymbolAddress((void**)&eidx,   g_eidx);
    cudaGetSymbolAddress((void**)&bsum,   g_bsum);

    // allow 72 KB dynamic smem for the GEMM (host attribute, not an alloc)
    static bool attr_done = false;
    if (!attr_done) {
        cudaFuncSetAttribute(mma_gemm_kernel,
                             cudaFuncAttributeMaxDynamicSharedMemorySize,
                             SMEM_BYTES);
        attr_done = true;
    }

    // h0 packed; out = bh2 (fused head)
    init_kernel<<<(NN * HP + 255) / 256, 256>>>(gate_type, emb, hPkA, out, bh2);

    // CSR build (graph static across layers)
    int nb = (NN + SB - 1) / SB;   // 196
    zero_int<<<(NN + 255) / 256, 256>>>(cursor, NN);
    count_kernel<<<(NE + 255) / 256, 256>>>(dst, cursor);
    scan_block<<<nb, SB>>>(cursor, offs, bsum, NN);
    scan_tops<<<1, SB>>>(bsum, nb);
    scan_add<<<(NN + 255) / 256, 256>>>(offs, bsum, cursor, NN);
    fill_kernel<<<(NE + 255) / 256, 256>>>(dst, cursor, eidx);

    // pack weights (once per launch)
    for (int l = 0; l < NL; l++) {
        pack_kernel<<<(256 * 128 + 255) / 256, 256>>>(
            W1 + (size_t)l * HD * W1_LD, W1_LD, 128, 256 * 128,
            W1p + (size_t)l * 256 * 128);
        pack_kernel<<<(256 * 256 + 255) / 256, 256>>>(
            W2 + (size_t)l * HD * W2_LD, W2_LD, 256, 256 * 256,
            W2p + (size_t)l * 256 * 256);
    }
    pack_kernel<<<(256 * 128 + 255) / 256, 256>>>(Wh1, HD, 128, 256 * 128, Wh1p);

    dim3 ggrid(HD / BN, (NN + BM - 1) / BM);   // (4, 782)
    uint2* hcur = hPkA;
    uint2* hnext = hPkB;

    for (int l = 0; l < NL; l++) {
        const float* W1l = W1 + (size_t)l * HD * W1_LD;
        const float* b2l = b2 + (size_t)l * HD;

        // P = h @ W1[:, :256]^T  (fp32 out, consumed by gather)
        mma_gemm_kernel<<<ggrid, 256, SMEM_BYTES>>>(
            hcur, HD, nullptr, 0, W1p + (size_t)l * 256 * 128,
            nullptr, P, nullptr, nullptr, nullptr, NN, HD, 0);

        // hNp[n] = pack(mean_e leaky(P[src] + w@W1b^T))  (gather, no atomics)
        csr_gather_kernel<<<(NN * 2 + 7) / 8, 256>>>(offs, eidx, src, w, P,
                                                     W1l + HD, hNp);

        // h' = relu([h | hNp] @ W2^T + b2) -> packed
        mma_gemm_kernel<<<ggrid, 256, SMEM_BYTES>>>(
            hcur, HD, hNp, HD, W2p + (size_t)l * 256 * 256,
            b2l, nullptr, hnext, nullptr, nullptr, NN, HD, 1);

        uint2* t = hcur; hcur = hnext; hnext = t;
    }

    // head fused: out[n] = bh2 + sum_c relu(h @ Wh1^T + bh1)[n,c] * Wh2[c]
    mma_gemm_kernel<<<ggrid, 256, SMEM_BYTES>>>(
        hcur, HD, nullptr, 0, Wh1p, bh1, nullptr, nullptr, Wh2, out,
        NN, HD, 1);
}